// round 17
// baseline (speedup 1.0000x reference)
#include <cuda_runtime.h>

// ConstrainNet residual:
//   out[0:64]            = V[0,:64] - x0
//   out[t*64 : t*64+64]  = [A B] @ V[t-1] - V[t,:64]   for t = 1..T-1
// Shapes: A (64,64), B (64,32), x0 (64), net_input = V (T=128, 96), out (T*64,)
//
// Champion shape (R5): 64 CTAs x 128 threads, thread = (s, kh). Each thread
// stages its 48-float AB row segment ONCE (12 LDG.128) and reuses it for
// BOTH timesteps: two independent 48-FMA/4-acc chains (ILP 2), one
// shfl_xor(1) each. Micro-change vs R5: after the shfl both lanes hold both
// dots, so kh=0 stores row t0 and kh=1 stores row t1 — one STG per lane,
// no divergent dual-store tail. No smem, no barriers.

constexpr int NS = 64;
constexpr int NA = 96;
constexpr int T  = 128;
constexpr int BT = 2;
constexpr int THREADS = 128;   // 64 rows * 2 k-halves

__global__ __launch_bounds__(THREADS, 1)
void constrainnet_kernel(const float* __restrict__ A,
                         const float* __restrict__ B,
                         const float* __restrict__ x0,
                         const float* __restrict__ V,
                         float* __restrict__ out) {
    const unsigned tid = threadIdx.x;
    const unsigned s   = tid >> 1;     // output row
    const unsigned kh  = tid & 1;      // k-half
    const int t0 = (int)(blockIdx.x * BT);
    const int t1 = t0 + 1;

    // Loads gating the final subtracts: issue immediately.
    const float vt0s = __ldg(&V[t0 * NA + s]);
    const float vt1s = __ldg(&V[t1 * NA + s]);
    const float x0s  = (t0 == 0) ? __ldg(&x0[s]) : 0.0f;

    // AB row s, k-segment [kh*48, kh*48+48):
    //   kh=0: A[s][0:16) | A[s][16:48)
    //   kh=1: A[s][48:64) | B[s][0:32)
    const float4* X4 = reinterpret_cast<const float4*>(A + s * 64 + kh * 48);
    const float4* Y4 = kh ? reinterpret_cast<const float4*>(B + s * 32)
                          : reinterpret_cast<const float4*>(A + s * 64 + 16);

    const int tp0 = (t0 > 0) ? (t0 - 1) : 0;   // clamped; t0==0 overridden
    const float4* Vp0 = reinterpret_cast<const float4*>(V + tp0 * NA + kh * 48);
    const float4* Vp1 = reinterpret_cast<const float4*>(V + t0  * NA + kh * 48);

    // Stage AB segment once (12 independent 128-bit loads).
    float4 ab[12];
    #pragma unroll
    for (int j = 0; j < 4; ++j) ab[j] = X4[j];
    #pragma unroll
    for (int j = 0; j < 8; ++j) ab[4 + j] = Y4[j];

    // Two independent 48-FMA dot products sharing the staged AB registers.
    float a0 = 0.f, a1 = 0.f, a2 = 0.f, a3 = 0.f;   // t0
    float c0 = 0.f, c1 = 0.f, c2 = 0.f, c3 = 0.f;   // t1
    #pragma unroll
    for (int j = 0; j < 12; ++j) {
        const float4 a = ab[j];
        float4 u = Vp0[j];
        float4 w = Vp1[j];
        a0 = fmaf(a.x, u.x, a0);
        a1 = fmaf(a.y, u.y, a1);
        a2 = fmaf(a.z, u.z, a2);
        a3 = fmaf(a.w, u.w, a3);
        c0 = fmaf(a.x, w.x, c0);
        c1 = fmaf(a.y, w.y, c1);
        c2 = fmaf(a.z, w.z, c2);
        c3 = fmaf(a.w, w.w, c3);
    }
    float dot0 = (a0 + a1) + (a2 + a3);
    float dot1 = (c0 + c1) + (c2 + c3);
    dot0 += __shfl_xor_sync(0xFFFFFFFFu, dot0, 1);
    dot1 += __shfl_xor_sync(0xFFFFFFFFu, dot1, 1);

    const float r0 = (t0 == 0) ? (vt0s - x0s) : (dot0 - vt0s);
    const float r1 = dot1 - vt1s;

    // Both lanes hold both results after the shfls: split the two stores.
    if (kh == 0) {
        out[t0 * NS + s] = r0;
    } else {
        out[t1 * NS + s] = r1;
    }
}

extern "C" void kernel_launch(void* const* d_in, const int* in_sizes, int n_in,
                              void* d_out, int out_size) {
    const float* A  = (const float*)d_in[0];
    const float* B  = (const float*)d_in[1];
    const float* x0 = (const float*)d_in[2];
    const float* V  = (const float*)d_in[3];
    float* out = (float*)d_out;

    constrainnet_kernel<<<T / BT, THREADS>>>(A, B, x0, V, out);
}